// round 14
// baseline (speedup 1.0000x reference)
#include <cuda_runtime.h>
#include <cstdint>
#include <cstddef>

// DynamicFC: out[b,o,h,w] = sum_i W[b,o,i] * X[b,i,h,w] + bias[b,o]
// B=64, Cin=Cout=512, HW=784, fp32.  Per-batch GEMM C[512,784] = W @ X + bias.
//
// R12 = R11 (ldmatrix A fragments) + R5 (B pre-rounded to tf32 at fill):
//  - A: cp.async into AST=36 layout; fragments via ldmatrix.m8n8.x4.b16
//    (2 per ks) + 8 cvt.rna.
//  - B: LDG.128 -> cvt.rna x4 -> STS.128 into BST=120 layout (register-staged,
//    one stage of LDG latency cover). Inner loop reads RAW bits: 14 LDS.32,
//    zero cvt.
//  - 2 A buffers + 2 B buffers, ONE __syncthreads per K-stage (R5 schedule).
// Tile 128x112x32, 256 thr, warp 32x56, 2 CTAs/SM. Same math as R4..R11.

#define COUT 512
#define CIN  512
#define HW   784

#define BM 128
#define BN 112
#define BK 32
#define NITERS (CIN / BK)     // 16

#define AST 36                // A smem row stride (floats): conflict-free
#define BST 120               // B smem row stride (floats): conflict-free
#define A_STAGE (BM * AST)    // 4608 floats
#define B_STAGE (BK * BST)    // 3840 floats
#define SMEM_FLOATS (2 * (A_STAGE + B_STAGE))   // 16896 floats = 67584 B

__device__ __forceinline__ uint32_t smem_u32(const void* p) {
    uint32_t a;
    asm("{ .reg .u64 t; cvta.to.shared.u64 t, %1; cvt.u32.u64 %0, t; }"
        : "=r"(a) : "l"(p));
    return a;
}
__device__ __forceinline__ uint32_t f2tf32(float x) {
    uint32_t u;
    asm("cvt.rna.tf32.f32 %0, %1;" : "=r"(u) : "f"(x));
    return u;
}
__device__ __forceinline__ void cpasync16(uint32_t s, const void* g) {
    asm volatile("cp.async.cg.shared.global [%0], [%1], 16;" :: "r"(s), "l"(g));
}
__device__ __forceinline__ void ldmatrix_x4(uint32_t& r0, uint32_t& r1,
                                            uint32_t& r2, uint32_t& r3,
                                            uint32_t addr) {
    asm volatile("ldmatrix.sync.aligned.m8n8.x4.shared.b16 {%0,%1,%2,%3}, [%4];"
                 : "=r"(r0), "=r"(r1), "=r"(r2), "=r"(r3) : "r"(addr));
}
__device__ __forceinline__ void mma1688(float* c, const uint32_t* a, const uint32_t* b) {
    asm volatile(
        "mma.sync.aligned.m16n8k8.row.col.f32.tf32.tf32.f32 "
        "{%0,%1,%2,%3}, {%4,%5,%6,%7}, {%8,%9}, {%0,%1,%2,%3};"
        : "+f"(c[0]), "+f"(c[1]), "+f"(c[2]), "+f"(c[3])
        : "r"(a[0]), "r"(a[1]), "r"(a[2]), "r"(a[3]), "r"(b[0]), "r"(b[1]));
}

// ---- A fill: cp.async, 128 rows x 32 k = 1024 float4 (4/thread) ------------
__device__ __forceinline__ void fillA(int st, int tid, uint32_t sb,
                                      const float* __restrict__ Wb) {
    const uint32_t aB = sb + (st & 1) * (A_STAGE * 4);
    const int k0 = st * BK;
#pragma unroll
    for (int i = 0; i < 4; i++) {
        const int c   = tid + i * 256;
        const int row = c >> 3;
        const int kb  = c & 7;
        cpasync16(aB + (row * AST + kb * 4) * 4,
                  Wb + (size_t)row * CIN + k0 + kb * 4);
    }
    asm volatile("cp.async.commit_group;" ::: "memory");
}

// ---- B fill: LDG.128 staging, then cvt.rna + STS.128 ------------------------
__device__ __forceinline__ void ldgB(int st, int tid, float4* r,
                                     const float* __restrict__ Xb, int n0) {
    const int k0 = st * BK;
#pragma unroll
    for (int i = 0; i < 4; i++) {
        const int q = tid + i * 256;
        if (q < 896) {
            const int k  = q / 28;
            const int ch = q - k * 28;
            r[i] = *reinterpret_cast<const float4*>(
                Xb + (size_t)(k0 + k) * HW + n0 + ch * 4);
        }
    }
}
__device__ __forceinline__ void stsB(int st, int tid, uint32_t sb, const float4* r) {
    const uint32_t bB = sb + 2 * (A_STAGE * 4) + (st & 1) * (B_STAGE * 4);
#pragma unroll
    for (int i = 0; i < 4; i++) {
        const int q = tid + i * 256;
        if (q < 896) {
            const int k  = q / 28;
            const int ch = q - k * 28;
            uint4 v;
            v.x = f2tf32(r[i].x); v.y = f2tf32(r[i].y);
            v.z = f2tf32(r[i].z); v.w = f2tf32(r[i].w);
            asm volatile("st.shared.v4.b32 [%0], {%1,%2,%3,%4};"
                         :: "r"(bB + (k * BST + ch * 4) * 4),
                            "r"(v.x), "r"(v.y), "r"(v.z), "r"(v.w) : "memory");
        }
    }
}

__global__ __launch_bounds__(256, 2)
void dynfc_tf32_kernel(const float* __restrict__ input,
                       const float* __restrict__ weight,
                       const float* __restrict__ bias,
                       float* __restrict__ out)
{
    extern __shared__ float smem[];
    const uint32_t sb = smem_u32(smem);

    const int tid  = threadIdx.x;
    const int wid  = tid >> 5;
    const int lane = tid & 31;
    const int g    = lane >> 2;      // 0..7
    const int tg   = lane & 3;       // 0..3
    const int wm   = wid >> 1;       // 0..3 (m warps, 32 rows)
    const int wn   = wid & 1;        // 0..1 (n warps, 56 cols)
    // ldmatrix lane->address mapping for the 16x8-tf32 A atom:
    const int rowA = lane & 15;          // row within atom
    const int colA = (lane >> 4) * 4;    // tf32 col offset (0 or 4)

    const int b  = blockIdx.z;
    const int m0 = blockIdx.y * BM;
    const int n0 = blockIdx.x * BN;

    const float* Wb = weight + ((size_t)b * COUT + m0) * CIN;
    const float* Xb = input  + (size_t)b * CIN * HW;

    // Accumulators: 2 m-atoms x 7 n-atoms x 4, bias folded into init.
    float acc[2][7][4];
#pragma unroll
    for (int am = 0; am < 2; am++) {
        const int r0 = m0 + wm * 32 + am * 16 + g;
        const float bv0 = bias[b * COUT + r0];
        const float bv1 = bias[b * COUT + r0 + 8];
#pragma unroll
        for (int j = 0; j < 7; j++) {
            acc[am][j][0] = bv0; acc[am][j][1] = bv0;
            acc[am][j][2] = bv1; acc[am][j][3] = bv1;
        }
    }

    float4 rB[4];

    // Prologue: A(0),A(1) async; B(0) direct; B(1) staged in regs.
    fillA(0, tid, sb, Wb);
    fillA(1, tid, sb, Wb);
    ldgB(0, tid, rB, Xb, n0);
    stsB(0, tid, sb, rB);
    ldgB(1, tid, rB, Xb, n0);
    asm volatile("cp.async.wait_group 0;" ::: "memory");
    __syncthreads();

    for (int s = 0; s < NITERS; s++) {
        const int buf = s & 1;
        const float* Bw = smem + 2 * A_STAGE + buf * B_STAGE + wn * 56;
        const uint32_t aAddr0 = sb + (buf * A_STAGE
                              + (wm * 32 + rowA) * AST + colA) * 4;
        const uint32_t aAddr1 = aAddr0 + 16 * AST * 4;

#pragma unroll
        for (int ks = 0; ks < BK / 8; ks++) {
            // B fragments: raw bits (pre-rounded at fill).
            uint32_t bfrag[7][2];
#pragma unroll
            for (int j = 0; j < 7; j++) {
                const float* bp = Bw + (ks * 8 + tg) * BST + j * 8 + g;
                bfrag[j][0] = __float_as_uint(bp[0]);
                bfrag[j][1] = __float_as_uint(bp[4 * BST]);
            }
            uint32_t afrag[2][4];
            ldmatrix_x4(afrag[0][0], afrag[0][1], afrag[0][2], afrag[0][3],
                        aAddr0 + ks * 8 * 4);
            ldmatrix_x4(afrag[1][0], afrag[1][1], afrag[1][2], afrag[1][3],
                        aAddr1 + ks * 8 * 4);
#pragma unroll
            for (int am = 0; am < 2; am++)
#pragma unroll
                for (int r = 0; r < 4; r++)
                    afrag[am][r] = f2tf32(__uint_as_float(afrag[am][r]));
#pragma unroll
            for (int am = 0; am < 2; am++)
#pragma unroll
                for (int j = 0; j < 7; j++)
                    mma1688(acc[am][j], afrag[am], bfrag[j]);
        }

        // Stage B(s+1) into the other buffer (no readers this stage).
        if (s + 1 < NITERS) stsB(s + 1, tid, sb, rB);
        // A(s+1) must be fully landed across all warps before next compute.
        asm volatile("cp.async.wait_group 0;" ::: "memory");
        __syncthreads();
        if (s + 2 < NITERS) {
            fillA(s + 2, tid, sb, Wb);        // overwrites buf s&1 (safe now)
            ldgB(s + 2, tid, rB, Xb, n0);     // consumed by stsB next stage
        }
    }

    // Epilogue: direct float2 stores (cols 2tg, 2tg+1 contiguous).
    float* Cb = out + (size_t)b * COUT * HW;
#pragma unroll
    for (int am = 0; am < 2; am++) {
        const int r0 = m0 + wm * 32 + am * 16 + g;
#pragma unroll
        for (int j = 0; j < 7; j++) {
            const int col = n0 + wn * 56 + j * 8 + 2 * tg;
            float2 v0 = make_float2(acc[am][j][0], acc[am][j][1]);
            float2 v1 = make_float2(acc[am][j][2], acc[am][j][3]);
            *reinterpret_cast<float2*>(Cb + (size_t)r0 * HW + col)       = v0;
            *reinterpret_cast<float2*>(Cb + (size_t)(r0 + 8) * HW + col) = v1;
        }
    }
}

extern "C" void kernel_launch(void* const* d_in, const int* in_sizes, int n_in,
                              void* d_out, int out_size)
{
    const float* input  = (const float*)d_in[0];  // (64, 512, 28, 28)
    const float* weight = (const float*)d_in[1];  // (64, 512, 512, 1, 1)
    const float* bias   = (const float*)d_in[2];  // (64, 512)
    float* out = (float*)d_out;

    cudaFuncSetAttribute(dynfc_tf32_kernel,
                         cudaFuncAttributeMaxDynamicSharedMemorySize,
                         SMEM_FLOATS * 4);
    dim3 grid(HW / BN, COUT / BM, 64);            // (7, 4, 64)
    dynfc_tf32_kernel<<<grid, 256, SMEM_FLOATS * 4>>>(input, weight, bias, out);
}